// round 10
// baseline (speedup 1.0000x reference)
#include <cuda_runtime.h>
#include <cuda_bf16.h>

#define NN 100000
#define EE 1600000

// Scratch (__device__ globals — no allocation allowed)
__device__ float4 g_t[NN * 8];     // ts = (h @ W) * dinv[row]
__device__ float4 g_h[NN * 8];     // hidden activations
__device__ float  g_dinv[NN];
__device__ int    g_deg[NN];
__device__ int    g_rowptr[NN + 1];
__device__ int    g_cur[NN];
__device__ int    g_srcs[EE];      // CSR-by-dst: src ids

// ---------------------------------------------------------------------------
__global__ void k_zero_cnt(int n) {
    int i = blockIdx.x * blockDim.x + threadIdx.x;
    if (i < n) g_deg[i] = 0;
}

__global__ void k_count(const int* __restrict__ dst, int E) {
    int e = blockIdx.x * blockDim.x + threadIdx.x;
    if (e < E) atomicAdd(&g_deg[dst[e]], 1);
}

// Single-block exclusive scan: g_deg -> g_rowptr/g_cur; dinv = rsqrt(deg+1)
__global__ void k_scan(int n) {
    __shared__ int warp_tot[32];
    __shared__ int s_carry;
    int tid = threadIdx.x;
    int lane = tid & 31, wid = tid >> 5;
    if (tid == 0) s_carry = 0;
    __syncthreads();

    for (int base = 0; base < n; base += 1024) {
        int i = base + tid;
        int v = (i < n) ? g_deg[i] : 0;

        int x = v;                       // inclusive warp scan
#pragma unroll
        for (int o = 1; o < 32; o <<= 1) {
            int y = __shfl_up_sync(0xffffffff, x, o);
            if (lane >= o) x += y;
        }
        if (lane == 31) warp_tot[wid] = x;
        __syncthreads();

        if (wid == 0) {
            int t = warp_tot[lane];
#pragma unroll
            for (int o = 1; o < 32; o <<= 1) {
                int y = __shfl_up_sync(0xffffffff, t, o);
                if (lane >= o) t += y;
            }
            warp_tot[lane] = t;
        }
        __syncthreads();

        int warp_off = (wid > 0) ? warp_tot[wid - 1] : 0;
        int excl = s_carry + warp_off + (x - v);
        if (i < n) {
            g_rowptr[i] = excl;
            g_cur[i]    = excl;
            g_dinv[i]   = rsqrtf((float)v + 1.0f);   // +1 self loop
        }
        __syncthreads();
        if (tid == 0) s_carry += warp_tot[31];
        __syncthreads();
    }
    if (threadIdx.x == 0) g_rowptr[n] = s_carry;
}

__global__ void k_fill(const int* __restrict__ src,
                       const int* __restrict__ dst, int E) {
    int e = blockIdx.x * blockDim.x + threadIdx.x;
    if (e < E) {
        int d = __ldg(&dst[e]);
        int p = atomicAdd(&g_cur[d], 1);
        g_srcs[p] = __ldg(&src[e]);
    }
}

// ---------------------------------------------------------------------------
// GEMM: T[row] = (X[row] @ W) * dinv[row] -> g_t.
// 4 threads/row, 8 cols each (4 packed f32x2 accs).
//   Layer 1: X = x, Wa = W1 [32x32], Wb = null.
//   Layer 2: X = null => read g_h; Wa = Wmu, Wb = Wlv (16+16 cols).
__global__ void k_gemm(const float4* __restrict__ X,
                       const float* __restrict__ Wa,
                       const float* __restrict__ Wb,
                       int n) {
    __shared__ __align__(16) unsigned long long Ws[32][16];
    int tid = threadIdx.x;
    for (int idx = tid; idx < 512; idx += blockDim.x) {
        int k  = idx >> 4;
        int cp = idx & 15;
        int c0 = cp * 2;
        float v0, v1;
        if (Wb == nullptr) {
            v0 = Wa[k * 32 + c0];
            v1 = Wa[k * 32 + c0 + 1];
        } else if (c0 < 16) {
            v0 = Wa[k * 16 + c0];
            v1 = Wa[k * 16 + c0 + 1];
        } else {
            v0 = Wb[k * 16 + (c0 - 16)];
            v1 = Wb[k * 16 + (c0 - 15)];
        }
        unsigned long long p;
        asm("mov.b64 %0, {%1,%2};" : "=l"(p) : "f"(v0), "f"(v1));
        Ws[k][cp] = p;
    }
    __syncthreads();

    int gid = blockIdx.x * blockDim.x + tid;
    int row = gid >> 2;
    int cg  = gid & 3;
    if (row >= n) return;

    const float4* xr = (X != nullptr) ? (X + (size_t)row * 8)
                                      : (g_h + (size_t)row * 8);
    float x[32];
#pragma unroll
    for (int q = 0; q < 8; q++) {
        float4 v = xr[q];
        x[4 * q + 0] = v.x; x[4 * q + 1] = v.y;
        x[4 * q + 2] = v.z; x[4 * q + 3] = v.w;
    }

    unsigned long long acc[4];
#pragma unroll
    for (int j = 0; j < 4; j++) acc[j] = 0ull;

    int cpb = cg * 4;
#pragma unroll
    for (int k = 0; k < 32; k++) {
        unsigned long long xk;
        asm("mov.b64 %0, {%1,%1};" : "=l"(xk) : "f"(x[k]));
        ulonglong2 w0 = *reinterpret_cast<const ulonglong2*>(&Ws[k][cpb]);
        ulonglong2 w1 = *reinterpret_cast<const ulonglong2*>(&Ws[k][cpb + 2]);
        asm("fma.rn.f32x2 %0, %1, %2, %0;" : "+l"(acc[0]) : "l"(xk), "l"(w0.x));
        asm("fma.rn.f32x2 %0, %1, %2, %0;" : "+l"(acc[1]) : "l"(xk), "l"(w0.y));
        asm("fma.rn.f32x2 %0, %1, %2, %0;" : "+l"(acc[2]) : "l"(xk), "l"(w1.x));
        asm("fma.rn.f32x2 %0, %1, %2, %0;" : "+l"(acc[3]) : "l"(xk), "l"(w1.y));
    }

    float di = g_dinv[row];
    unsigned long long d2;
    asm("mov.b64 %0, {%1,%1};" : "=l"(d2) : "f"(di));
    float o[8];
#pragma unroll
    for (int j = 0; j < 4; j++) {
        asm("mul.rn.f32x2 %0, %0, %1;" : "+l"(acc[j]) : "l"(d2));
        asm("mov.b64 {%0,%1}, %2;"
            : "=f"(o[2 * j]), "=f"(o[2 * j + 1]) : "l"(acc[j]));
    }

    size_t base = (size_t)row * 8 + cg * 2;
    g_t[base]     = make_float4(o[0], o[1], o[2], o[3]);
    g_t[base + 1] = make_float4(o[4], o[5], o[6], o[7]);
}

// ---------------------------------------------------------------------------
// CSR gather core: 8 lanes per node (channel quad c), register accumulation.
// Batches of 8 neighbors: ONE coalesced LDG.32 per lane fetches 8 indices for
// the group; group-masked SHFL distributes them; 8 independent LDG.128
// gathers in flight (MLP 8/group, 32/warp — saturates LTS, hides ~380cyc L2).
// No atomics at all; one store per node-quad at the end.
__device__ __forceinline__ float4 gather_core(int i, int c, unsigned gmask,
                                              int gbase) {
    int beg = g_rowptr[i];
    int end = g_rowptr[i + 1];
    float4 acc = g_t[(size_t)i * 8 + c];     // self-loop term
    int j = beg;
    for (; j + 8 <= end; j += 8) {
        int myidx = __ldg(&g_srcs[j + c]);   // lane c loads index j+c
        int s0 = __shfl_sync(gmask, myidx, gbase + 0);
        int s1 = __shfl_sync(gmask, myidx, gbase + 1);
        int s2 = __shfl_sync(gmask, myidx, gbase + 2);
        int s3 = __shfl_sync(gmask, myidx, gbase + 3);
        int s4 = __shfl_sync(gmask, myidx, gbase + 4);
        int s5 = __shfl_sync(gmask, myidx, gbase + 5);
        int s6 = __shfl_sync(gmask, myidx, gbase + 6);
        int s7 = __shfl_sync(gmask, myidx, gbase + 7);
        float4 v0 = g_t[(size_t)s0 * 8 + c];
        float4 v1 = g_t[(size_t)s1 * 8 + c];
        float4 v2 = g_t[(size_t)s2 * 8 + c];
        float4 v3 = g_t[(size_t)s3 * 8 + c];
        float4 v4 = g_t[(size_t)s4 * 8 + c];
        float4 v5 = g_t[(size_t)s5 * 8 + c];
        float4 v6 = g_t[(size_t)s6 * 8 + c];
        float4 v7 = g_t[(size_t)s7 * 8 + c];
        acc.x += (v0.x + v1.x) + (v2.x + v3.x) + ((v4.x + v5.x) + (v6.x + v7.x));
        acc.y += (v0.y + v1.y) + (v2.y + v3.y) + ((v4.y + v5.y) + (v6.y + v7.y));
        acc.z += (v0.z + v1.z) + (v2.z + v3.z) + ((v4.z + v5.z) + (v6.z + v7.z));
        acc.w += (v0.w + v1.w) + (v2.w + v3.w) + ((v4.w + v5.w) + (v6.w + v7.w));
    }
    for (; j < end; j++) {                   // tail (avg ~4)
        int s = __ldg(&g_srcs[j]);
        float4 v = g_t[(size_t)s * 8 + c];
        acc.x += v.x; acc.y += v.y; acc.z += v.z; acc.w += v.w;
    }
    return acc;
}

// layer 1: h = relu(dinv * acc + b1) -> g_h
__global__ void k_gather1(const float* __restrict__ b, int n) {
    int gid = blockIdx.x * blockDim.x + threadIdx.x;
    int i = gid >> 3;
    if (i >= n) return;
    int lane = threadIdx.x & 31;
    int c = lane & 7;
    int gbase = lane & ~7;
    unsigned gmask = 0xFFu << gbase;
    float4 acc = gather_core(i, c, gmask, gbase);
    float di = g_dinv[i];
    float4 bb = ((const float4*)b)[c];
    float4 r;
    r.x = fmaxf(fmaf(di, acc.x, bb.x), 0.f);
    r.y = fmaxf(fmaf(di, acc.y, bb.y), 0.f);
    r.z = fmaxf(fmaf(di, acc.z, bb.z), 0.f);
    r.w = fmaxf(fmaf(di, acc.w, bb.w), 0.f);
    g_h[(size_t)i * 8 + c] = r;
}

// layer 2: mu -> out[0:N*16], logvar -> out[N*16:]
__global__ void k_gather2(const float* __restrict__ bmu,
                          const float* __restrict__ blv,
                          float* __restrict__ out, int n) {
    int gid = blockIdx.x * blockDim.x + threadIdx.x;
    int i = gid >> 3;
    if (i >= n) return;
    int lane = threadIdx.x & 31;
    int c = lane & 7;
    int gbase = lane & ~7;
    unsigned gmask = 0xFFu << gbase;
    float4 acc = gather_core(i, c, gmask, gbase);
    float di = g_dinv[i];
    float4 r;
    if (c < 4) {
        float4 bb = ((const float4*)bmu)[c];
        r.x = fmaf(di, acc.x, bb.x);
        r.y = fmaf(di, acc.y, bb.y);
        r.z = fmaf(di, acc.z, bb.z);
        r.w = fmaf(di, acc.w, bb.w);
        ((float4*)out)[(size_t)i * 4 + c] = r;
    } else {
        float4 bb = ((const float4*)blv)[c - 4];
        r.x = fmaf(di, acc.x, bb.x);
        r.y = fmaf(di, acc.y, bb.y);
        r.z = fmaf(di, acc.z, bb.z);
        r.w = fmaf(di, acc.w, bb.w);
        ((float4*)(out + (size_t)n * 16))[(size_t)i * 4 + (c - 4)] = r;
    }
}

// ---------------------------------------------------------------------------
extern "C" void kernel_launch(void* const* d_in, const int* in_sizes, int n_in,
                              void* d_out, int out_size) {
    const float* x   = (const float*)d_in[0];
    const int*   ei  = (const int*)d_in[1];
    const float* W1  = (const float*)d_in[2];
    const float* b1  = (const float*)d_in[3];
    const float* Wmu = (const float*)d_in[4];
    const float* bmu = (const float*)d_in[5];
    const float* Wlv = (const float*)d_in[6];
    const float* blv = (const float*)d_in[7];
    float* out = (float*)d_out;

    int N = in_sizes[0] / 32;
    int E = in_sizes[1] / 2;
    const int* src = ei;          // edge_index row 0
    const int* dst = ei + E;      // edge_index row 1

    const int TB = 256;
    int gN  = (N + TB - 1) / TB;
    int gE  = (E + TB - 1) / TB;
    int gN4 = (int)(((long long)N * 4 + TB - 1) / TB);
    int gN8 = (int)(((long long)N * 8 + TB - 1) / TB);

    // CSR build (by dst) + dinv; count doubles as degree
    k_zero_cnt<<<gN, TB>>>(N);
    k_count   <<<gE, TB>>>(dst, E);
    k_scan    <<<1, 1024>>>(N);

    // gemm1 does not need the CSR fill — order it before fill for no stall
    k_gemm    <<<gN4, TB>>>((const float4*)x, W1, nullptr, N);
    k_fill    <<<gE, TB>>>(src, dst, E);

    // layer 1 aggregate (fused bias+relu)
    k_gather1 <<<gN8, TB>>>(b1, N);

    // layer 2: gemm(mu|lv) then aggregate (fused bias + mu/lv split)
    k_gemm    <<<gN4, TB>>>(nullptr, Wmu, Wlv, N);
    k_gather2 <<<gN8, TB>>>(bmu, blv, out, N);
}

// round 11
// speedup vs baseline: 2.1279x; 2.1279x over previous
#include <cuda_runtime.h>
#include <cuda_bf16.h>

#define NN 100000
#define EE 1600000

// Scratch (__device__ globals — no allocation allowed)
__device__ float4 g_t[NN * 8];     // ts = (h @ W) * dinv[row]
__device__ float4 g_agg[NN * 8];   // accumulator, seeded with ts (self loop)
__device__ float  g_degf[NN];      // degree (float, includes +1 self loop)

// ---------------------------------------------------------------------------
// deg = 1 (self loop)
__global__ void k_init(int n) {
    int i = blockIdx.x * blockDim.x + threadIdx.x;
    if (i < n) g_degf[i] = 1.0f;
}

// deg count over destinations (plain RED, no return)
__global__ void k_deg(const int* __restrict__ dst, int E) {
    int e = blockIdx.x * blockDim.x + threadIdx.x;
    if (e < E) atomicAdd(&g_degf[dst[e]], 1.0f);
}

// ---------------------------------------------------------------------------
// GEMM: T[row] = (X[row] @ W) * dinv[row], written to BOTH g_t and g_agg
// (g_agg seed = self-loop term).
// 4 threads per row, 8 output cols each (4 packed f32x2 accumulators).
// x-row LDGs are issued BEFORE the weight-smem fill + barrier so their
// DRAM/L2 latency overlaps the prologue (front-batched MLP=8+).
//   Layer 1: X = input x, Wa = W1 [32x32], Wb = null, bias = null.
//   Layer 2: X = null => row input = relu(dinv*g_agg[row] + bias) computed
//            inline after the barrier (fused post1); Wa = Wmu, Wb = Wlv.
__global__ void k_gemm(const float4* __restrict__ X,
                       const float* __restrict__ Wa,
                       const float* __restrict__ Wb,
                       const float* __restrict__ bias,
                       int n) {
    __shared__ __align__(16) unsigned long long Ws[32][16];
    __shared__ float bs[32];
    int tid = threadIdx.x;
    int gid = blockIdx.x * blockDim.x + tid;
    int row = gid >> 2;
    int cg  = gid & 3;                       // column group: cols 8cg..8cg+7
    bool alive = (row < n);
    int rrow = alive ? row : 0;              // clamp: keep loads in-bounds,
                                             // all threads reach the barrier

    // ---- front-batched row + degree loads (overlap smem prologue) ----
    const float4* xr = (X != nullptr) ? (X + (size_t)rrow * 8)
                                      : (g_agg + (size_t)rrow * 8);
    float4 xv0 = xr[0], xv1 = xr[1], xv2 = xr[2], xv3 = xr[3];
    float4 xv4 = xr[4], xv5 = xr[5], xv6 = xr[6], xv7 = xr[7];
    float dg = g_degf[rrow];

    // ---- stage W (packed f32x2 pairs) + bias into smem ----
    for (int idx = tid; idx < 512; idx += blockDim.x) {
        int k  = idx >> 4;
        int cp = idx & 15;
        int c0 = cp * 2;
        float v0, v1;
        if (Wb == nullptr) {                 // layer 1: W1 [32x32]
            v0 = Wa[k * 32 + c0];
            v1 = Wa[k * 32 + c0 + 1];
        } else if (c0 < 16) {                // layer 2 cols 0-15: Wmu [32x16]
            v0 = Wa[k * 16 + c0];
            v1 = Wa[k * 16 + c0 + 1];
        } else {                             // layer 2 cols 16-31: Wlv [32x16]
            v0 = Wb[k * 16 + (c0 - 16)];
            v1 = Wb[k * 16 + (c0 - 15)];
        }
        unsigned long long p;
        asm("mov.b64 %0, {%1,%2};" : "=l"(p) : "f"(v0), "f"(v1));
        Ws[k][cp] = p;
    }
    if (tid < 32) bs[tid] = (bias != nullptr) ? bias[tid] : 0.0f;
    __syncthreads();

    if (!alive) return;

    float di = rsqrtf(dg);

    float x[32];
    {
        float4 t;
        t = xv0; x[0]=t.x; x[1]=t.y; x[2]=t.z; x[3]=t.w;
        t = xv1; x[4]=t.x; x[5]=t.y; x[6]=t.z; x[7]=t.w;
        t = xv2; x[8]=t.x; x[9]=t.y; x[10]=t.z; x[11]=t.w;
        t = xv3; x[12]=t.x; x[13]=t.y; x[14]=t.z; x[15]=t.w;
        t = xv4; x[16]=t.x; x[17]=t.y; x[18]=t.z; x[19]=t.w;
        t = xv5; x[20]=t.x; x[21]=t.y; x[22]=t.z; x[23]=t.w;
        t = xv6; x[24]=t.x; x[25]=t.y; x[26]=t.z; x[27]=t.w;
        t = xv7; x[28]=t.x; x[29]=t.y; x[30]=t.z; x[31]=t.w;
    }
    if (X == nullptr) {                      // fused post1: relu(di*agg + b1)
#pragma unroll
        for (int j = 0; j < 32; j++)
            x[j] = fmaxf(fmaf(di, x[j], bs[j]), 0.0f);
    }

    unsigned long long acc[4];
#pragma unroll
    for (int j = 0; j < 4; j++) acc[j] = 0ull;

    int cpb = cg * 4;
#pragma unroll
    for (int k = 0; k < 32; k++) {
        unsigned long long xk;
        asm("mov.b64 %0, {%1,%1};" : "=l"(xk) : "f"(x[k]));
        ulonglong2 w0 = *reinterpret_cast<const ulonglong2*>(&Ws[k][cpb]);
        ulonglong2 w1 = *reinterpret_cast<const ulonglong2*>(&Ws[k][cpb + 2]);
        asm("fma.rn.f32x2 %0, %1, %2, %0;" : "+l"(acc[0]) : "l"(xk), "l"(w0.x));
        asm("fma.rn.f32x2 %0, %1, %2, %0;" : "+l"(acc[1]) : "l"(xk), "l"(w0.y));
        asm("fma.rn.f32x2 %0, %1, %2, %0;" : "+l"(acc[2]) : "l"(xk), "l"(w1.x));
        asm("fma.rn.f32x2 %0, %1, %2, %0;" : "+l"(acc[3]) : "l"(xk), "l"(w1.y));
    }

    unsigned long long d2;
    asm("mov.b64 %0, {%1,%1};" : "=l"(d2) : "f"(di));
    float o[8];
#pragma unroll
    for (int j = 0; j < 4; j++) {
        asm("mul.rn.f32x2 %0, %0, %1;" : "+l"(acc[j]) : "l"(d2));
        asm("mov.b64 {%0,%1}, %2;"
            : "=f"(o[2 * j]), "=f"(o[2 * j + 1]) : "l"(acc[j]));
    }

    float4 r0 = make_float4(o[0], o[1], o[2], o[3]);
    float4 r1 = make_float4(o[4], o[5], o[6], o[7]);
    size_t base = (size_t)row * 8 + cg * 2;
    g_t[base]       = r0;
    g_t[base + 1]   = r1;
    g_agg[base]     = r0;   // self-loop seed
    g_agg[base + 1] = r1;
}

// ---------------------------------------------------------------------------
// AGG[dst] += T[src].
// Each warp owns 32 edges: indices front-loaded into registers (2 coalesced
// LDG wavefronts per 32 edges), distributed via SHFL (no L1tex wavefront
// cost). 8 independent iterations x 4 edges x 8 lanes: lanes 8k..8k+7 cover
// one edge's full 128B row (coalesced gather + RED.128).
__global__ void k_scatter(const int* __restrict__ src,
                          const int* __restrict__ dst, int E) {
    int warp = (blockIdx.x * blockDim.x + threadIdx.x) >> 5;
    int lane = threadIdx.x & 31;
    int base = warp * 32;
    if (base >= E) return;

    int e = base + lane;
    int sreg = (e < E) ? __ldg(&src[e]) : 0;
    int dreg = (e < E) ? __ldg(&dst[e]) : 0;

    int c   = lane & 7;      // channel quad within row
    int sub = lane >> 3;     // which of 4 edges this iteration

    if (base + 32 <= E) {
#pragma unroll
        for (int it = 0; it < 8; it++) {
            int eloc = it * 4 + sub;
            int s = __shfl_sync(0xffffffff, sreg, eloc);
            int d = __shfl_sync(0xffffffff, dreg, eloc);
            float4 v = g_t[(size_t)s * 8 + c];
            float4* p = g_agg + (size_t)d * 8 + c;
            asm volatile("red.global.add.v4.f32 [%0], {%1,%2,%3,%4};"
                         :: "l"(p), "f"(v.x), "f"(v.y), "f"(v.z), "f"(v.w)
                         : "memory");
        }
    } else {
#pragma unroll
        for (int it = 0; it < 8; it++) {
            int eloc = it * 4 + sub;
            int s = __shfl_sync(0xffffffff, sreg, eloc);
            int d = __shfl_sync(0xffffffff, dreg, eloc);
            if (base + eloc < E) {
                float4 v = g_t[(size_t)s * 8 + c];
                float4* p = g_agg + (size_t)d * 8 + c;
                asm volatile("red.global.add.v4.f32 [%0], {%1,%2,%3,%4};"
                             :: "l"(p), "f"(v.x), "f"(v.y), "f"(v.z), "f"(v.w)
                             : "memory");
            }
        }
    }
}

// ---------------------------------------------------------------------------
// final: mu -> out[0:N*16], logvar -> out[N*16:]
// out = dinv * agg + bias   (agg already contains self-loop term)
__global__ void k_post2(const float* __restrict__ bmu,
                        const float* __restrict__ blv,
                        float* __restrict__ out, int n) {
    int gid = blockIdx.x * blockDim.x + threadIdx.x;
    int i = gid >> 3;
    if (i >= n) return;
    int c = gid & 7;
    float di = rsqrtf(g_degf[i]);
    float4 a = g_agg[(size_t)i * 8 + c];
    float4 r;
    if (c < 4) {
        float4 bb = ((const float4*)bmu)[c];
        r.x = fmaf(di, a.x, bb.x);
        r.y = fmaf(di, a.y, bb.y);
        r.z = fmaf(di, a.z, bb.z);
        r.w = fmaf(di, a.w, bb.w);
        ((float4*)out)[(size_t)i * 4 + c] = r;
    } else {
        float4 bb = ((const float4*)blv)[c - 4];
        r.x = fmaf(di, a.x, bb.x);
        r.y = fmaf(di, a.y, bb.y);
        r.z = fmaf(di, a.z, bb.z);
        r.w = fmaf(di, a.w, bb.w);
        ((float4*)(out + (size_t)n * 16))[(size_t)i * 4 + (c - 4)] = r;
    }
}

// ---------------------------------------------------------------------------
extern "C" void kernel_launch(void* const* d_in, const int* in_sizes, int n_in,
                              void* d_out, int out_size) {
    const float* x   = (const float*)d_in[0];
    const int*   ei  = (const int*)d_in[1];
    const float* W1  = (const float*)d_in[2];
    const float* b1  = (const float*)d_in[3];
    const float* Wmu = (const float*)d_in[4];
    const float* bmu = (const float*)d_in[5];
    const float* Wlv = (const float*)d_in[6];
    const float* blv = (const float*)d_in[7];
    float* out = (float*)d_out;

    int N = in_sizes[0] / 32;
    int E = in_sizes[1] / 2;
    const int* src = ei;          // edge_index row 0
    const int* dst = ei + E;      // edge_index row 1

    const int TB = 256;
    int gN  = (N + TB - 1) / TB;
    int gE  = (E + TB - 1) / TB;
    int gN4 = (int)(((long long)N * 4 + TB - 1) / TB);   // gemm: 4 thr/row
    int gN8 = (int)(((long long)N * 8 + TB - 1) / TB);
    int gEw = (int)(((long long)E + TB - 1) / TB);       // 32 edges per warp

    // degrees (dinv computed inline via rsqrtf where needed)
    k_init<<<gN, TB>>>(N);
    k_deg <<<gE, TB>>>(dst, E);

    // layer 1: t1 -> g_t, g_agg (seeded); scatter adds neighbor terms
    k_gemm   <<<gN4, TB>>>((const float4*)x, W1, nullptr, nullptr, N);
    k_scatter<<<gEw, TB>>>(src, dst, E);

    // layer 2: fused relu(dinv*agg + b1) -> GEMM(mu|lv) -> re-seed agg
    k_gemm   <<<gN4, TB>>>(nullptr, Wmu, Wlv, b1, N);
    k_scatter<<<gEw, TB>>>(src, dst, E);

    // final bias + dinv scale, split mu / logvar
    k_post2<<<gN8, TB>>>(bmu, blv, out, N);
}

// round 14
// speedup vs baseline: 2.1344x; 1.0031x over previous
#include <cuda_runtime.h>
#include <cuda_fp16.h>
#include <cuda_bf16.h>

#define NN 100000
#define EE 1600000

// Scratch (__device__ globals — no allocation allowed)
// g_t16: message values in fp16 (gather payload) — 32 halves (64B) per row,
// stored as 8 x uint2 (4 halves each).
__device__ uint2  g_t16[NN * 8];
__device__ float4 g_agg[NN * 8];   // fp32 accumulator, seeded with self-loop ts
__device__ float  g_degf[NN];      // degree (float, includes +1 self loop)

// ---------------------------------------------------------------------------
// deg = 1 (self loop)
__global__ void k_init(int n) {
    int i = blockIdx.x * blockDim.x + threadIdx.x;
    if (i < n) g_degf[i] = 1.0f;
}

// deg count over destinations (plain RED, no return)
__global__ void k_deg(const int* __restrict__ dst, int E) {
    int e = blockIdx.x * blockDim.x + threadIdx.x;
    if (e < E) atomicAdd(&g_degf[dst[e]], 1.0f);
}

// ---------------------------------------------------------------------------
// GEMM: T[row] = (X[row] @ W) * dinv[row].
//   -> g_agg  (fp32, self-loop seed, full precision)
//   -> g_t16  (fp16, gather payload for the scatter)
// 4 threads/row, 8 cols each (4 packed f32x2 accumulators); x-row LDGs
// front-batched before the smem prologue.
//   Layer 1: X = x, Wa = W1 [32x32], Wb = null, bias = null.
//   Layer 2: X = null => row = relu(dinv*g_agg[row] + bias) (fused post1);
//            Wa = Wmu, Wb = Wlv (16+16 cols).
__global__ void k_gemm(const float4* __restrict__ X,
                       const float* __restrict__ Wa,
                       const float* __restrict__ Wb,
                       const float* __restrict__ bias,
                       int n) {
    __shared__ __align__(16) unsigned long long Ws[32][16];
    __shared__ float bs[32];
    int tid = threadIdx.x;
    int gid = blockIdx.x * blockDim.x + tid;
    int row = gid >> 2;
    int cg  = gid & 3;
    bool alive = (row < n);
    int rrow = alive ? row : 0;

    // front-batched row + degree loads (overlap smem prologue)
    const float4* xr = (X != nullptr) ? (X + (size_t)rrow * 8)
                                      : (g_agg + (size_t)rrow * 8);
    float4 xv0 = xr[0], xv1 = xr[1], xv2 = xr[2], xv3 = xr[3];
    float4 xv4 = xr[4], xv5 = xr[5], xv6 = xr[6], xv7 = xr[7];
    float dg = g_degf[rrow];

    // stage W (packed f32x2 pairs) + bias into smem
    for (int idx = tid; idx < 512; idx += blockDim.x) {
        int k  = idx >> 4;
        int cp = idx & 15;
        int c0 = cp * 2;
        float v0, v1;
        if (Wb == nullptr) {                 // layer 1: W1 [32x32]
            v0 = Wa[k * 32 + c0];
            v1 = Wa[k * 32 + c0 + 1];
        } else if (c0 < 16) {                // layer 2 cols 0-15: Wmu
            v0 = Wa[k * 16 + c0];
            v1 = Wa[k * 16 + c0 + 1];
        } else {                             // layer 2 cols 16-31: Wlv
            v0 = Wb[k * 16 + (c0 - 16)];
            v1 = Wb[k * 16 + (c0 - 15)];
        }
        unsigned long long p;
        asm("mov.b64 %0, {%1,%2};" : "=l"(p) : "f"(v0), "f"(v1));
        Ws[k][cp] = p;
    }
    if (tid < 32) bs[tid] = (bias != nullptr) ? bias[tid] : 0.0f;
    __syncthreads();

    if (!alive) return;

    float di = rsqrtf(dg);

    float x[32];
    {
        float4 t;
        t = xv0; x[0]=t.x; x[1]=t.y; x[2]=t.z; x[3]=t.w;
        t = xv1; x[4]=t.x; x[5]=t.y; x[6]=t.z; x[7]=t.w;
        t = xv2; x[8]=t.x; x[9]=t.y; x[10]=t.z; x[11]=t.w;
        t = xv3; x[12]=t.x; x[13]=t.y; x[14]=t.z; x[15]=t.w;
        t = xv4; x[16]=t.x; x[17]=t.y; x[18]=t.z; x[19]=t.w;
        t = xv5; x[20]=t.x; x[21]=t.y; x[22]=t.z; x[23]=t.w;
        t = xv6; x[24]=t.x; x[25]=t.y; x[26]=t.z; x[27]=t.w;
        t = xv7; x[28]=t.x; x[29]=t.y; x[30]=t.z; x[31]=t.w;
    }
    if (X == nullptr) {                      // fused post1: relu(di*agg + b1)
#pragma unroll
        for (int j = 0; j < 32; j++)
            x[j] = fmaxf(fmaf(di, x[j], bs[j]), 0.0f);
    }

    unsigned long long acc[4];
#pragma unroll
    for (int j = 0; j < 4; j++) acc[j] = 0ull;

    int cpb = cg * 4;
#pragma unroll
    for (int k = 0; k < 32; k++) {
        unsigned long long xk;
        asm("mov.b64 %0, {%1,%1};" : "=l"(xk) : "f"(x[k]));
        ulonglong2 w0 = *reinterpret_cast<const ulonglong2*>(&Ws[k][cpb]);
        ulonglong2 w1 = *reinterpret_cast<const ulonglong2*>(&Ws[k][cpb + 2]);
        asm("fma.rn.f32x2 %0, %1, %2, %0;" : "+l"(acc[0]) : "l"(xk), "l"(w0.x));
        asm("fma.rn.f32x2 %0, %1, %2, %0;" : "+l"(acc[1]) : "l"(xk), "l"(w0.y));
        asm("fma.rn.f32x2 %0, %1, %2, %0;" : "+l"(acc[2]) : "l"(xk), "l"(w1.x));
        asm("fma.rn.f32x2 %0, %1, %2, %0;" : "+l"(acc[3]) : "l"(xk), "l"(w1.y));
    }

    unsigned long long d2;
    asm("mov.b64 %0, {%1,%1};" : "=l"(d2) : "f"(di));
    float o[8];
#pragma unroll
    for (int j = 0; j < 4; j++) {
        asm("mul.rn.f32x2 %0, %0, %1;" : "+l"(acc[j]) : "l"(d2));
        asm("mov.b64 {%0,%1}, %2;"
            : "=f"(o[2 * j]), "=f"(o[2 * j + 1]) : "l"(acc[j]));
    }

    // fp32 seed (self-loop term, unquantized)
    size_t base = (size_t)row * 8 + cg * 2;
    g_agg[base]     = make_float4(o[0], o[1], o[2], o[3]);
    g_agg[base + 1] = make_float4(o[4], o[5], o[6], o[7]);

    // fp16 gather payload (bit-cast half2 -> u32 via reinterpret, no intrinsic)
    __half2 h0 = __floats2half2_rn(o[0], o[1]);
    __half2 h1 = __floats2half2_rn(o[2], o[3]);
    __half2 h2 = __floats2half2_rn(o[4], o[5]);
    __half2 h3 = __floats2half2_rn(o[6], o[7]);
    uint2 p0, p1;
    p0.x = *reinterpret_cast<unsigned int*>(&h0);
    p0.y = *reinterpret_cast<unsigned int*>(&h1);
    p1.x = *reinterpret_cast<unsigned int*>(&h2);
    p1.y = *reinterpret_cast<unsigned int*>(&h3);
    g_t16[base]     = p0;
    g_t16[base + 1] = p1;
}

// ---------------------------------------------------------------------------
// AGG[dst] += T16[src]  (fp16 gather, fp32 vector reduction).
// Warp owns 32 edges: indices front-loaded (2 coalesced LDG wavefronts /
// 32 edges), SHFL-distributed. 8 independent iterations x 4 edges x 8 lanes;
// lanes 8k..8k+7 cover one edge's 64B fp16 row (LDG.64) and its 128B fp32
// accumulator row (RED.128).
__global__ void k_scatter(const int* __restrict__ src,
                          const int* __restrict__ dst, int E) {
    int warp = (blockIdx.x * blockDim.x + threadIdx.x) >> 5;
    int lane = threadIdx.x & 31;
    int base = warp * 32;
    if (base >= E) return;

    int e = base + lane;
    int sreg = (e < E) ? __ldg(&src[e]) : 0;
    int dreg = (e < E) ? __ldg(&dst[e]) : 0;

    int c   = lane & 7;      // channel quad within row
    int sub = lane >> 3;     // which of 4 edges this iteration

    if (base + 32 <= E) {
#pragma unroll
        for (int it = 0; it < 8; it++) {
            int eloc = it * 4 + sub;
            int s = __shfl_sync(0xffffffff, sreg, eloc);
            int d = __shfl_sync(0xffffffff, dreg, eloc);
            uint2 pv = g_t16[(size_t)s * 8 + c];
            __half2 ha = *reinterpret_cast<__half2*>(&pv.x);
            __half2 hb = *reinterpret_cast<__half2*>(&pv.y);
            float2 f0 = __half22float2(ha);
            float2 f1 = __half22float2(hb);
            float4* p = g_agg + (size_t)d * 8 + c;
            asm volatile("red.global.add.v4.f32 [%0], {%1,%2,%3,%4};"
                         :: "l"(p), "f"(f0.x), "f"(f0.y), "f"(f1.x), "f"(f1.y)
                         : "memory");
        }
    } else {
#pragma unroll
        for (int it = 0; it < 8; it++) {
            int eloc = it * 4 + sub;
            int s = __shfl_sync(0xffffffff, sreg, eloc);
            int d = __shfl_sync(0xffffffff, dreg, eloc);
            if (base + eloc < E) {
                uint2 pv = g_t16[(size_t)s * 8 + c];
                __half2 ha = *reinterpret_cast<__half2*>(&pv.x);
                __half2 hb = *reinterpret_cast<__half2*>(&pv.y);
                float2 f0 = __half22float2(ha);
                float2 f1 = __half22float2(hb);
                float4* p = g_agg + (size_t)d * 8 + c;
                asm volatile("red.global.add.v4.f32 [%0], {%1,%2,%3,%4};"
                             :: "l"(p), "f"(f0.x), "f"(f0.y), "f"(f1.x), "f"(f1.y)
                             : "memory");
            }
        }
    }
}

// ---------------------------------------------------------------------------
// final: mu -> out[0:N*16], logvar -> out[N*16:]
// out = dinv * agg + bias   (agg already contains self-loop term)
__global__ void k_post2(const float* __restrict__ bmu,
                        const float* __restrict__ blv,
                        float* __restrict__ out, int n) {
    int gid = blockIdx.x * blockDim.x + threadIdx.x;
    int i = gid >> 3;
    if (i >= n) return;
    int c = gid & 7;
    float di = rsqrtf(g_degf[i]);
    float4 a = g_agg[(size_t)i * 8 + c];
    float4 r;
    if (c < 4) {
        float4 bb = ((const float4*)bmu)[c];
        r.x = fmaf(di, a.x, bb.x);
        r.y = fmaf(di, a.y, bb.y);
        r.z = fmaf(di, a.z, bb.z);
        r.w = fmaf(di, a.w, bb.w);
        ((float4*)out)[(size_t)i * 4 + c] = r;
    } else {
        float4 bb = ((const float4*)blv)[c - 4];
        r.x = fmaf(di, a.x, bb.x);
        r.y = fmaf(di, a.y, bb.y);
        r.z = fmaf(di, a.z, bb.z);
        r.w = fmaf(di, a.w, bb.w);
        ((float4*)(out + (size_t)n * 16))[(size_t)i * 4 + (c - 4)] = r;
    }
}

// ---------------------------------------------------------------------------
extern "C" void kernel_launch(void* const* d_in, const int* in_sizes, int n_in,
                              void* d_out, int out_size) {
    const float* x   = (const float*)d_in[0];
    const int*   ei  = (const int*)d_in[1];
    const float* W1  = (const float*)d_in[2];
    const float* b1  = (const float*)d_in[3];
    const float* Wmu = (const float*)d_in[4];
    const float* bmu = (const float*)d_in[5];
    const float* Wlv = (const float*)d_in[6];
    const float* blv = (const float*)d_in[7];
    float* out = (float*)d_out;

    int N = in_sizes[0] / 32;
    int E = in_sizes[1] / 2;
    const int* src = ei;          // edge_index row 0
    const int* dst = ei + E;      // edge_index row 1

    const int TB = 256;
    int gN  = (N + TB - 1) / TB;
    int gE  = (E + TB - 1) / TB;
    int gN4 = (int)(((long long)N * 4 + TB - 1) / TB);   // gemm: 4 thr/row
    int gN8 = (int)(((long long)N * 8 + TB - 1) / TB);
    int gEw = (int)(((long long)E + TB - 1) / TB);       // 32 edges per warp

    // degrees (dinv computed inline via rsqrtf where needed)
    k_init<<<gN, TB>>>(N);
    k_deg <<<gE, TB>>>(dst, E);

    // layer 1: t1 -> g_t16 (fp16) + g_agg seed (fp32); scatter adds neighbors
    k_gemm   <<<gN4, TB>>>((const float4*)x, W1, nullptr, nullptr, N);
    k_scatter<<<gEw, TB>>>(src, dst, E);

    // layer 2: fused relu(dinv*agg + b1) -> GEMM(mu|lv) -> re-seed
    k_gemm   <<<gN4, TB>>>(nullptr, Wmu, Wlv, b1, N);
    k_scatter<<<gEw, TB>>>(src, dst, E);

    // final bias + dinv scale, split mu / logvar
    k_post2<<<gN8, TB>>>(bmu, blv, out, N);
}